// round 15
// baseline (speedup 1.0000x reference)
#include <cuda_runtime.h>
#include <cuda_bf16.h>

// actions: [B=4096, T=256, A=64] fp32
// out[b,0,a] = x[b,0,a]
// out[b,t,a] = out[b,t-1,a] + clip(x[b,t,a] - x[b,t-1,a], -0.5, 0.5)
//
// Decoupled segmented scan, quarter-row CTAs. The A dimension is independent:
// each batch row is split across 4 CTAs (4 float4 lanes each). 16384 CTAs x
// 128 threads, CHUNK=8, ~50 regs, __launch_bounds__(128,8) -> 8 CTAs/SM:
// EIGHT independent phase clocks per SM (R10 had 4 -> DRAM 81.5%; R6 had
// 2 -> 78.9%). Same 32 warps/SM; phases half as long as R10.
//  Phase 1:  dep-free load of 8 float4/thread (warp = 8 contiguous 64B segs).
//  Phase 2a: in-register local scan.
//  Phase 2b: warp w (0..3) shuffle-scans the 32 chunk sums of lane w.
//  Phase 3:  streaming store.

#define TT     256
#define ROW4   16            // float4 lanes per full (b,t) row
#define LANES  4             // float4 lanes owned by this CTA
#define CHUNK  8             // timesteps per thread
#define NCHUNK (TT / CHUNK)  // 32
#define MAXD   0.5f

__device__ __forceinline__ float4 clip4(const float4 a, const float4 b)
{
    float4 d;
    d.x = fminf(fmaxf(a.x - b.x, -MAXD), MAXD);
    d.y = fminf(fmaxf(a.y - b.y, -MAXD), MAXD);
    d.z = fminf(fmaxf(a.z - b.z, -MAXD), MAXD);
    d.w = fminf(fmaxf(a.w - b.w, -MAXD), MAXD);
    return d;
}

__device__ __forceinline__ float4 add4(const float4 a, const float4 b)
{
    return make_float4(a.x + b.x, a.y + b.y, a.z + b.z, a.w + b.w);
}

__device__ __forceinline__ float4 shfl_up4(const float4 v, int off)
{
    float4 r;
    r.x = __shfl_up_sync(0xffffffffu, v.x, off);
    r.y = __shfl_up_sync(0xffffffffu, v.y, off);
    r.z = __shfl_up_sync(0xffffffffu, v.z, off);
    r.w = __shfl_up_sync(0xffffffffu, v.w, off);
    return r;
}

__global__ __launch_bounds__(128, 8) void smooth_scan_kernel(
    const float4* __restrict__ in, float4* __restrict__ out)
{
    __shared__ float4 s_last[NCHUNK][LANES + 1];  // raw x at chunk's last t
    __shared__ float4 s_pref[NCHUNK][LANES + 1];  // chunk sums -> excl prefixes

    const unsigned blk  = blockIdx.x;
    const unsigned b    = blk >> 2;          // batch row
    const unsigned quad = blk & 3;           // which 4-lane quarter of the row
    const unsigned tid  = threadIdx.x;
    const unsigned a4   = tid & 3;           // lane within quarter (0..3)
    const unsigned c    = tid >> 2;          // time chunk (0..31)
    const unsigned w    = tid >> 5;          // warp id (0..3)
    const unsigned lid  = tid & 31;          // lane in warp

    const size_t base = (size_t)b * (TT * ROW4)
                      + (size_t)c * (CHUNK * ROW4)
                      + quad * LANES + a4;

    // ---- Phase 1: dependency-free streaming load ----
    float4 x[CHUNK];
    #pragma unroll
    for (int i = 0; i < CHUNK; ++i)
        x[i] = in[base + (size_t)i * ROW4];

    s_last[c][a4] = x[CHUNK - 1];
    __syncthreads();

    // ---- Phase 2a: in-place local scan ----
    // chunk 0: v[0] = x[0] (carries the base term); chunk c>0: v[0] = clipped
    // diff vs previous chunk's last raw x. v[i] = v[i-1] + clip(x[i]-x[i-1]).
    {
        float4 raw_prev = x[0];
        if (c != 0) {
            float4 xp = s_last[c - 1][a4];
            x[0] = clip4(raw_prev, xp);
        }
        #pragma unroll
        for (int i = 1; i < CHUNK; ++i) {
            float4 cur = x[i];
            x[i] = add4(x[i - 1], clip4(cur, raw_prev));
            raw_prev = cur;
        }
    }

    // ---- Phase 2b: exclusive scan of 32 chunk sums, warp w -> lane w ----
    s_pref[c][a4] = x[CHUNK - 1];
    __syncthreads();

    {
        float4 v = s_pref[lid][w];          // lane lid holds chunk lid's sum
        #pragma unroll
        for (int off = 1; off < 32; off <<= 1) {
            float4 n = shfl_up4(v, off);
            if ((int)lid >= off) v = add4(v, n);
        }
        float4 e = shfl_up4(v, 1);          // exclusive shift
        if (lid == 0) e = make_float4(0.f, 0.f, 0.f, 0.f);
        s_pref[lid][w] = e;
    }
    __syncthreads();

    const float4 P = s_pref[c][a4];

    // ---- Phase 3: streaming store ----
    #pragma unroll
    for (int i = 0; i < CHUNK; ++i)
        out[base + (size_t)i * ROW4] = add4(x[i], P);
}

extern "C" void kernel_launch(void* const* d_in, const int* in_sizes, int n_in,
                              void* d_out, int out_size)
{
    const float4* in  = (const float4*)d_in[0];
    float4*       out = (float4*)d_out;

    smooth_scan_kernel<<<4096 * 4, 128>>>(in, out);  // 16384 x 128
}

// round 16
// speedup vs baseline: 1.0004x; 1.0004x over previous
#include <cuda_runtime.h>
#include <cuda_bf16.h>

// actions: [B=4096, T=256, A=64] fp32
// out[b,0,a] = x[b,0,a]
// out[b,t,a] = out[b,t-1,a] + clip(x[b,t,a] - x[b,t-1,a], -0.5, 0.5)
//
// R10 geometry (best measured: kernel 74.6us, DRAM 81.5%): half-row CTAs,
// 8192 CTAs x 256 threads, LANES=8, CHUNK=8, 4 independent phase clocks/SM.
// R16 delta: __ldcs/__stcs streaming hints — both streams are read-once/
// write-once, so evict-first should cut dead L2 fill. (R2's .cs regression
// was confounded by a float2 width change; this isolates the hint.)

#define TT     256
#define ROW4   16            // float4 lanes per full (b,t) row
#define LANES  8             // float4 lanes owned by this CTA
#define CHUNK  8             // timesteps per thread
#define NCHUNK (TT / CHUNK)  // 32
#define MAXD   0.5f

__device__ __forceinline__ float4 clip4(const float4 a, const float4 b)
{
    float4 d;
    d.x = fminf(fmaxf(a.x - b.x, -MAXD), MAXD);
    d.y = fminf(fmaxf(a.y - b.y, -MAXD), MAXD);
    d.z = fminf(fmaxf(a.z - b.z, -MAXD), MAXD);
    d.w = fminf(fmaxf(a.w - b.w, -MAXD), MAXD);
    return d;
}

__device__ __forceinline__ float4 add4(const float4 a, const float4 b)
{
    return make_float4(a.x + b.x, a.y + b.y, a.z + b.z, a.w + b.w);
}

__device__ __forceinline__ float4 shfl_up4(const float4 v, int off)
{
    float4 r;
    r.x = __shfl_up_sync(0xffffffffu, v.x, off);
    r.y = __shfl_up_sync(0xffffffffu, v.y, off);
    r.z = __shfl_up_sync(0xffffffffu, v.z, off);
    r.w = __shfl_up_sync(0xffffffffu, v.w, off);
    return r;
}

__global__ __launch_bounds__(256, 4) void smooth_scan_kernel(
    const float4* __restrict__ in, float4* __restrict__ out)
{
    __shared__ float4 s_last[NCHUNK][LANES + 1];  // raw x at chunk's last t
    __shared__ float4 s_pref[NCHUNK][LANES + 1];  // chunk sums -> excl prefixes

    const unsigned blk  = blockIdx.x;
    const unsigned b    = blk >> 1;          // batch row
    const unsigned half = blk & 1;           // which 8-lane half of the row
    const unsigned tid  = threadIdx.x;
    const unsigned a4   = tid & 7;           // lane within half-row (0..7)
    const unsigned c    = tid >> 3;          // time chunk (0..31)
    const unsigned w    = tid >> 5;          // warp id (0..7)
    const unsigned lid  = tid & 31;          // lane in warp

    const size_t base = (size_t)b * (TT * ROW4)
                      + (size_t)c * (CHUNK * ROW4)
                      + half * LANES + a4;

    // ---- Phase 1: dependency-free streaming load (evict-first) ----
    float4 x[CHUNK];
    #pragma unroll
    for (int i = 0; i < CHUNK; ++i)
        x[i] = __ldcs(&in[base + (size_t)i * ROW4]);

    s_last[c][a4] = x[CHUNK - 1];
    __syncthreads();

    // ---- Phase 2a: in-place local scan ----
    // chunk 0: v[0] = x[0] (carries the base term); chunk c>0: v[0] = clipped
    // diff vs previous chunk's last raw x. v[i] = v[i-1] + clip(x[i]-x[i-1]).
    {
        float4 raw_prev = x[0];
        if (c != 0) {
            float4 xp = s_last[c - 1][a4];
            x[0] = clip4(raw_prev, xp);
        }
        #pragma unroll
        for (int i = 1; i < CHUNK; ++i) {
            float4 cur = x[i];
            x[i] = add4(x[i - 1], clip4(cur, raw_prev));
            raw_prev = cur;
        }
    }

    // ---- Phase 2b: exclusive scan of 32 chunk sums, warp w -> lane w ----
    s_pref[c][a4] = x[CHUNK - 1];
    __syncthreads();

    {
        float4 v = s_pref[lid][w];          // lane lid holds chunk lid's sum
        #pragma unroll
        for (int off = 1; off < 32; off <<= 1) {
            float4 n = shfl_up4(v, off);
            if ((int)lid >= off) v = add4(v, n);
        }
        float4 e = shfl_up4(v, 1);          // exclusive shift
        if (lid == 0) e = make_float4(0.f, 0.f, 0.f, 0.f);
        s_pref[lid][w] = e;
    }
    __syncthreads();

    const float4 P = s_pref[c][a4];

    // ---- Phase 3: streaming store (evict-first) ----
    #pragma unroll
    for (int i = 0; i < CHUNK; ++i)
        __stcs(&out[base + (size_t)i * ROW4], add4(x[i], P));
}

extern "C" void kernel_launch(void* const* d_in, const int* in_sizes, int n_in,
                              void* d_out, int out_size)
{
    const float4* in  = (const float4*)d_in[0];
    float4*       out = (float4*)d_out;

    smooth_scan_kernel<<<4096 * 2, 256>>>(in, out);  // 8192 x 256
}